// round 11
// baseline (speedup 1.0000x reference)
#include <cuda_runtime.h>

#define Bn   2
#define Tn   7
#define Hn   128
#define Wn   128
#define Pn   343            // 7*7*7 taps
#define Un   16
#define HW   (Hn*Wn)        // 16384
#define WT   16             // w-tile per block
#define RL   24             // padded patch row length (WT+6=22 -> 24)
#define CSTR (49*RL)        // channel stride in smem (floats)
#define NT   64             // threads per block

// R10: R3's proven inner loop (front-batched float4 LDG x7 taps) with SMALL
// blocks for full-grid residency. Grid 2048, 14 blocks/SM resident (smem
// 14.1KB x14 = 198KB, regs <=73) -> single wave, no trailing tail.
// R3's 134us had 6.92 blocks work/SM but only 6 resident -> ~15% tail idle.
// Block: 64 thr = 16 u x 4 w-groups (float4). Fused softmax-without-max,
// filt (719MB) streamed exactly once with __ldcs.
__global__ __launch_bounds__(NT, 14)
void dynfilt_kernel(const float* __restrict__ x,
                    const float* __restrict__ filt,
                    float* __restrict__ out)
{
    __shared__ float sm[3 * CSTR];   // 14.1 KB

    const int bx    = blockIdx.x;
    const int wq    = bx & 7;            // w eighth
    const int h     = (bx >> 3) & 127;   // row
    const int b     = bx >> 10;          // batch
    const int tid   = threadIdx.x;
    const int u     = tid >> 2;          // 0..15
    const int wg    = tid & 3;           // 0..3 -> w0 = 4*wg
    const int wbase = wq * WT;

    // ---- stage x patches: sm[(c*49 + t*7 + kh)*RL + j], j in [0,22), pad 0 ----
    for (int idx = tid; idx < 3 * 49 * RL; idx += NT) {
        int j   = idx % RL;
        int r   = idx / RL;          // c*49 + row
        int row = r % 49;            // t*7 + kh
        int c   = r / 49;
        int t   = row / 7;
        int kh  = row % 7;
        int gh  = h + kh - 3;
        int gw  = wbase + j - 3;
        float v = 0.f;
        if (j < WT + 6 && (unsigned)gh < (unsigned)Hn && (unsigned)gw < (unsigned)Wn)
            v = x[(((size_t)(b * 3 + c) * Tn + t) * Hn + gh) * Wn + gw];
        sm[idx] = v;
    }
    __syncthreads();

    float acc[3][4] = {{0.f,0.f,0.f,0.f},{0.f,0.f,0.f,0.f},{0.f,0.f,0.f,0.f}};
    float ls[4]     = {0.f, 0.f, 0.f, 0.f};

    // filt[b, p, u, h, w]; per-tap stride = Un*HW elems (1 MB).
    const size_t TAP = (size_t)Un * HW;
    const float* fp = filt + (((size_t)b * Pn) * Un + (size_t)u) * HW
                           + (size_t)h * Wn + wbase + 4 * wg;

    #pragma unroll 1
    for (int r = 0; r < 49; ++r) {
        const float* srow = sm + r * RL + 4 * wg;   // 16B aligned

        // ---- front-batch all 7 tap loads of this row (LDG.128) ----
        float4 f[7];
        #pragma unroll
        for (int i = 0; i < 7; ++i)
            f[i] = __ldcs((const float4*)(fp + (size_t)i * TAP));

        // ---- patch window [0..11] for 3 channels ----
        float pw[3][12];
        #pragma unroll
        for (int c = 0; c < 3; ++c) {
            float4 q0 = *(const float4*)(srow + c * CSTR);
            float4 q1 = *(const float4*)(srow + c * CSTR + 4);
            float4 q2 = *(const float4*)(srow + c * CSTR + 8);
            pw[c][0] = q0.x; pw[c][1]  = q0.y; pw[c][2]  = q0.z; pw[c][3]  = q0.w;
            pw[c][4] = q1.x; pw[c][5]  = q1.y; pw[c][6]  = q1.z; pw[c][7]  = q1.w;
            pw[c][8] = q2.x; pw[c][9]  = q2.y; pw[c][10] = q2.z; pw[c][11] = q2.w;
        }

        // ---- compute: 7 taps x 4 w ----
        #pragma unroll
        for (int kw = 0; kw < 7; ++kw) {
            float e0 = __expf(f[kw].x);
            float e1 = __expf(f[kw].y);
            float e2 = __expf(f[kw].z);
            float e3 = __expf(f[kw].w);
            ls[0] += e0; ls[1] += e1; ls[2] += e2; ls[3] += e3;
            #pragma unroll
            for (int c = 0; c < 3; ++c) {
                acc[c][0] += e0 * pw[c][kw];
                acc[c][1] += e1 * pw[c][kw + 1];
                acc[c][2] += e2 * pw[c][kw + 2];
                acc[c][3] += e3 * pw[c][kw + 3];
            }
        }

        fp += 7 * TAP;
    }

    // ---- epilogue: normalize + pixel shuffle ----
    // u -> (ur=u/4, uc=u%4); thread w's are wbase+4wg+i -> out col 4*w + uc.
    const int ur = u >> 2, uc = u & 3;
    const int Ho = Hn * 4, Wo = Wn * 4;
    const size_t cstride = (size_t)Ho * Wo;
    size_t obase = ((size_t)(b * 3) * Ho + (4 * h + ur)) * Wo
                 + (size_t)4 * (wbase + 4 * wg) + uc;

    #pragma unroll
    for (int i = 0; i < 4; ++i) {
        float inv = 1.f / ls[i];
        out[obase + 4 * i]               = acc[0][i] * inv;
        out[obase + 4 * i + cstride]     = acc[1][i] * inv;
        out[obase + 4 * i + 2 * cstride] = acc[2][i] * inv;
    }
}

extern "C" void kernel_launch(void* const* d_in, const int* in_sizes, int n_in,
                              void* d_out, int out_size)
{
    const float* x    = (const float*)d_in[0];   // [2,3,7,128,128]
    const float* filt = (const float*)d_in[1];   // [2,343,16,128,128]
    float* out        = (float*)d_out;           // [2,3,512,512]

    // Max smem carveout so 14 blocks/SM (198 KB) actually fit.
    static bool configured = false;
    if (!configured) {
        cudaFuncSetAttribute(dynfilt_kernel,
                             cudaFuncAttributePreferredSharedMemoryCarveout, 100);
        configured = true;
    }

    // grid = B * H * (W/WT) = 2*128*8 = 2048 blocks, 64 threads each.
    // 148 SMs x 14 resident = 2072 >= 2048 -> single wave, no tail.
    dynfilt_kernel<<<Bn * Hn * (Wn / WT), NT>>>(x, filt, out);
}

// round 12
// speedup vs baseline: 1.4159x; 1.4159x over previous
#include <cuda_runtime.h>

#define Bn   2
#define Tn   7
#define Hn   128
#define Wn   128
#define Pn   343            // 7*7*7 taps
#define Un   16
#define HW   (Hn*Wn)        // 16384
#define WT   32             // w-tile per block
#define RL   40             // padded row length (needs >= WT+12 for float4 tail)
#define CSTR (49*RL)        // channel stride in smem (floats)

// R12 = R3 (best: 133.9us) + max smem carveout.
// R3 asked for 7 blocks/SM but default L1/smem carveout capped it at 6
// (occ 37.9% ~= 24 warps). 7 x 24.1KB = 169KB needs carveout raised.
// With 7/SM: 148*7 = 1036 >= 1024 grid -> SINGLE WAVE, no straggler tail,
// +17% resident warps. R10 lesson: never cap regs below ~72 (spills).
//
// Block: one (b, h, 32-wide w tile). 128 threads = 16 u x 8 w-groups.
// Each thread: ONE u, FOUR contiguous w (LDG.128 on filt).
// Fused softmax-without-max single pass: filt (719MB) streamed exactly once.
__global__ __launch_bounds__(128, 7)
void dynfilt_kernel(const float* __restrict__ x,
                    const float* __restrict__ filt,
                    float* __restrict__ out)
{
    __shared__ float sm[3 * CSTR];

    const int bx    = blockIdx.x;
    const int wq    = bx & 3;            // w quarter
    const int h     = (bx >> 2) & 127;   // row
    const int b     = bx >> 9;           // batch
    const int tid   = threadIdx.x;
    const int u     = tid >> 3;          // 0..15
    const int wg    = tid & 7;           // 0..7  -> w0 = 4*wg within tile
    const int wbase = wq * WT;

    // ---- stage x patches: sm[(c*49 + t*7 + kh)*RL + j], j in [0,38), pad 0 ----
    for (int idx = tid; idx < 3 * 49 * RL; idx += 128) {
        int j   = idx % RL;
        int r   = idx / RL;          // c*49 + row
        int row = r % 49;            // t*7 + kh
        int c   = r / 49;
        int t   = row / 7;
        int kh  = row % 7;
        int gh  = h + kh - 3;
        int gw  = wbase + j - 3;
        float v = 0.f;
        if (j < WT + 6 && (unsigned)gh < (unsigned)Hn && (unsigned)gw < (unsigned)Wn)
            v = x[(((size_t)(b * 3 + c) * Tn + t) * Hn + gh) * Wn + gw];
        sm[idx] = v;
    }
    __syncthreads();

    float acc0[4] = {0.f, 0.f, 0.f, 0.f};   // channel 0, w0..w0+3
    float acc1[4] = {0.f, 0.f, 0.f, 0.f};
    float acc2[4] = {0.f, 0.f, 0.f, 0.f};
    float lsum[4] = {0.f, 0.f, 0.f, 0.f};

    // filt[b, p, u, h, w]; per-tap stride = Un*HW elems (1 MB).
    const size_t TAP = (size_t)Un * HW;
    const float* fp = filt + (((size_t)b * Pn) * Un + (size_t)u) * HW
                           + (size_t)h * Wn + wbase + 4 * wg;

    #pragma unroll 1
    for (int r = 0; r < 49; ++r) {
        const float* srow = sm + r * RL + 4 * wg;   // 16B aligned (RL*4=160)

        // ---- phase A: stage 4 taps (LDG.128) + patch window [0..7] ----
        float4 f0 = __ldcs((const float4*)(fp + 0 * TAP));
        float4 f1 = __ldcs((const float4*)(fp + 1 * TAP));
        float4 f2 = __ldcs((const float4*)(fp + 2 * TAP));
        float4 f3 = __ldcs((const float4*)(fp + 3 * TAP));

        float pw[3][12];
        #pragma unroll
        for (int c = 0; c < 3; ++c) {
            float4 q0 = *(const float4*)(srow + c * CSTR);
            float4 q1 = *(const float4*)(srow + c * CSTR + 4);
            pw[c][0] = q0.x; pw[c][1] = q0.y; pw[c][2] = q0.z; pw[c][3] = q0.w;
            pw[c][4] = q1.x; pw[c][5] = q1.y; pw[c][6] = q1.z; pw[c][7] = q1.w;
        }

        float4 fq[4] = {f0, f1, f2, f3};
        #pragma unroll
        for (int kw = 0; kw < 4; ++kw) {
            float e0 = __expf(fq[kw].x);
            float e1 = __expf(fq[kw].y);
            float e2 = __expf(fq[kw].z);
            float e3 = __expf(fq[kw].w);
            lsum[0] += e0; lsum[1] += e1; lsum[2] += e2; lsum[3] += e3;
            acc0[0] += e0 * pw[0][kw];     acc0[1] += e1 * pw[0][kw + 1];
            acc0[2] += e2 * pw[0][kw + 2]; acc0[3] += e3 * pw[0][kw + 3];
            acc1[0] += e0 * pw[1][kw];     acc1[1] += e1 * pw[1][kw + 1];
            acc1[2] += e2 * pw[1][kw + 2]; acc1[3] += e3 * pw[1][kw + 3];
            acc2[0] += e0 * pw[2][kw];     acc2[1] += e1 * pw[2][kw + 1];
            acc2[2] += e2 * pw[2][kw + 2]; acc2[3] += e3 * pw[2][kw + 3];
        }

        // ---- phase B: 3 taps + patch window [8..11] ----
        float4 g0 = __ldcs((const float4*)(fp + 4 * TAP));
        float4 g1 = __ldcs((const float4*)(fp + 5 * TAP));
        float4 g2 = __ldcs((const float4*)(fp + 6 * TAP));

        #pragma unroll
        for (int c = 0; c < 3; ++c) {
            float4 q2 = *(const float4*)(srow + c * CSTR + 8);
            pw[c][8] = q2.x; pw[c][9] = q2.y; pw[c][10] = q2.z; pw[c][11] = q2.w;
        }

        float4 gq[3] = {g0, g1, g2};
        #pragma unroll
        for (int k = 0; k < 3; ++k) {
            int kw = k + 4;
            float e0 = __expf(gq[k].x);
            float e1 = __expf(gq[k].y);
            float e2 = __expf(gq[k].z);
            float e3 = __expf(gq[k].w);
            lsum[0] += e0; lsum[1] += e1; lsum[2] += e2; lsum[3] += e3;
            acc0[0] += e0 * pw[0][kw];     acc0[1] += e1 * pw[0][kw + 1];
            acc0[2] += e2 * pw[0][kw + 2]; acc0[3] += e3 * pw[0][kw + 3];
            acc1[0] += e0 * pw[1][kw];     acc1[1] += e1 * pw[1][kw + 1];
            acc1[2] += e2 * pw[1][kw + 2]; acc1[3] += e3 * pw[1][kw + 3];
            acc2[0] += e0 * pw[2][kw];     acc2[1] += e1 * pw[2][kw + 1];
            acc2[2] += e2 * pw[2][kw + 2]; acc2[3] += e3 * pw[2][kw + 3];
        }

        fp += 7 * TAP;
    }

    // ---- epilogue: normalize + pixel shuffle ----
    // u -> (ur = u/4, uc = u%4); thread w's are wbase+4wg+i.
    const int ur = u >> 2, uc = u & 3;
    const int Ho = Hn * 4, Wo = Wn * 4;
    const size_t cstride = (size_t)Ho * Wo;
    size_t obase = ((size_t)(b * 3) * Ho + (4 * h + ur)) * Wo
                 + (size_t)4 * (wbase + 4 * wg) + uc;

    #pragma unroll
    for (int i = 0; i < 4; ++i) {
        float inv = 1.f / lsum[i];
        out[obase + 4 * i]                = acc0[i] * inv;
        out[obase + 4 * i + cstride]      = acc1[i] * inv;
        out[obase + 4 * i + 2 * cstride]  = acc2[i] * inv;
    }
}

extern "C" void kernel_launch(void* const* d_in, const int* in_sizes, int n_in,
                              void* d_out, int out_size)
{
    const float* x    = (const float*)d_in[0];   // [2,3,7,128,128]
    const float* filt = (const float*)d_in[1];   // [2,343,16,128,128]
    float* out        = (float*)d_out;           // [2,3,512,512]

    // Raise L1/smem carveout so 7 blocks x 24.1KB = 169KB fit per SM.
    static bool configured = false;
    if (!configured) {
        cudaFuncSetAttribute(dynfilt_kernel,
                             cudaFuncAttributePreferredSharedMemoryCarveout, 100);
        configured = true;
    }

    // grid = B * H * (W/WT) = 2*128*4 = 1024 blocks, 128 threads each.
    // 148 SMs x 7 resident = 1036 >= 1024 -> single wave, no tail.
    dynfilt_kernel<<<Bn * Hn * (Wn / WT), 128>>>(x, filt, out);
}

// round 13
// speedup vs baseline: 1.8095x; 1.2780x over previous
#include <cuda_runtime.h>
#include <cuda_fp16.h>

#define Bn   2
#define Tn   7
#define Hn   128
#define Wn   128
#define Pn   343            // 7*7*7 taps
#define Un   16
#define HW   (Hn*Wn)        // 16384
#define WT   32             // w-tile per block
#define RL   40             // padded row length (halves)
#define CSTR (49*RL)        // channel stride in patch smem (halves)

// R13 = R3 (best: 133.9us) with fp16 patch smem: 24.1KB -> 12.0KB so SEVEN
// blocks fit per SM under the DEFAULT carveout (R12 proved carveout=100
// kills LDG MLP -> never max it). 148x7 = 1036 >= 1024 grid -> single wave,
// no straggler tail, 28 warps/SM instead of 24.
// filt path untouched: fp32 LDG.128, __ldcs, 7 taps front-batched per row.
// Patch fp16 quantization: ~3e-4 global rel err, well under 1e-3.
__global__ __launch_bounds__(128, 7)
void dynfilt_kernel(const float* __restrict__ x,
                    const float* __restrict__ filt,
                    float* __restrict__ out)
{
    __shared__ __half sm[3 * CSTR];   // 11.8 KB

    const int bx    = blockIdx.x;
    const int wq    = bx & 3;            // w quarter
    const int h     = (bx >> 2) & 127;   // row
    const int b     = bx >> 9;           // batch
    const int tid   = threadIdx.x;
    const int u     = tid >> 3;          // 0..15
    const int wg    = tid & 7;           // 0..7  -> w0 = 4*wg within tile
    const int wbase = wq * WT;

    // ---- stage x patches (fp16): sm[(c*49+t*7+kh)*RL + j], j in [0,38), pad 0
    for (int idx = tid; idx < 3 * 49 * RL; idx += 128) {
        int j   = idx % RL;
        int r   = idx / RL;          // c*49 + row
        int row = r % 49;            // t*7 + kh
        int c   = r / 49;
        int t   = row / 7;
        int kh  = row % 7;
        int gh  = h + kh - 3;
        int gw  = wbase + j - 3;
        float v = 0.f;
        if (j < WT + 6 && (unsigned)gh < (unsigned)Hn && (unsigned)gw < (unsigned)Wn)
            v = x[(((size_t)(b * 3 + c) * Tn + t) * Hn + gh) * Wn + gw];
        sm[idx] = __float2half(v);
    }
    __syncthreads();

    float acc0[4] = {0.f, 0.f, 0.f, 0.f};   // channel 0, w0..w0+3
    float acc1[4] = {0.f, 0.f, 0.f, 0.f};
    float acc2[4] = {0.f, 0.f, 0.f, 0.f};
    float lsum[4] = {0.f, 0.f, 0.f, 0.f};

    // filt[b, p, u, h, w]; per-tap stride = Un*HW elems (1 MB).
    const size_t TAP = (size_t)Un * HW;
    const float* fp = filt + (((size_t)b * Pn) * Un + (size_t)u) * HW
                           + (size_t)h * Wn + wbase + 4 * wg;

    #pragma unroll 1
    for (int r = 0; r < 49; ++r) {
        // srow at half-index r*RL + 4wg: even -> half2-aligned.
        const __half2* srow = (const __half2*)(sm + r * RL + 4 * wg);

        // ---- phase A: stage 4 taps (LDG.128) + patch window [0..7] ----
        float4 f0 = __ldcs((const float4*)(fp + 0 * TAP));
        float4 f1 = __ldcs((const float4*)(fp + 1 * TAP));
        float4 f2 = __ldcs((const float4*)(fp + 2 * TAP));
        float4 f3 = __ldcs((const float4*)(fp + 3 * TAP));

        float pw[3][12];
        #pragma unroll
        for (int c = 0; c < 3; ++c) {
            const __half2* sp = srow + c * (CSTR / 2);
            #pragma unroll
            for (int k = 0; k < 4; ++k) {
                float2 d = __half22float2(sp[k]);
                pw[c][2 * k]     = d.x;
                pw[c][2 * k + 1] = d.y;
            }
        }

        float4 fq[4] = {f0, f1, f2, f3};
        #pragma unroll
        for (int kw = 0; kw < 4; ++kw) {
            float e0 = __expf(fq[kw].x);
            float e1 = __expf(fq[kw].y);
            float e2 = __expf(fq[kw].z);
            float e3 = __expf(fq[kw].w);
            lsum[0] += e0; lsum[1] += e1; lsum[2] += e2; lsum[3] += e3;
            acc0[0] += e0 * pw[0][kw];     acc0[1] += e1 * pw[0][kw + 1];
            acc0[2] += e2 * pw[0][kw + 2]; acc0[3] += e3 * pw[0][kw + 3];
            acc1[0] += e0 * pw[1][kw];     acc1[1] += e1 * pw[1][kw + 1];
            acc1[2] += e2 * pw[1][kw + 2]; acc1[3] += e3 * pw[1][kw + 3];
            acc2[0] += e0 * pw[2][kw];     acc2[1] += e1 * pw[2][kw + 1];
            acc2[2] += e2 * pw[2][kw + 2]; acc2[3] += e3 * pw[2][kw + 3];
        }

        // ---- phase B: 3 taps + patch window [8..11] ----
        float4 g0 = __ldcs((const float4*)(fp + 4 * TAP));
        float4 g1 = __ldcs((const float4*)(fp + 5 * TAP));
        float4 g2 = __ldcs((const float4*)(fp + 6 * TAP));

        #pragma unroll
        for (int c = 0; c < 3; ++c) {
            const __half2* sp = srow + c * (CSTR / 2);
            #pragma unroll
            for (int k = 4; k < 6; ++k) {
                float2 d = __half22float2(sp[k]);
                pw[c][2 * k]     = d.x;
                pw[c][2 * k + 1] = d.y;
            }
        }

        float4 gq[3] = {g0, g1, g2};
        #pragma unroll
        for (int k = 0; k < 3; ++k) {
            int kw = k + 4;
            float e0 = __expf(gq[k].x);
            float e1 = __expf(gq[k].y);
            float e2 = __expf(gq[k].z);
            float e3 = __expf(gq[k].w);
            lsum[0] += e0; lsum[1] += e1; lsum[2] += e2; lsum[3] += e3;
            acc0[0] += e0 * pw[0][kw];     acc0[1] += e1 * pw[0][kw + 1];
            acc0[2] += e2 * pw[0][kw + 2]; acc0[3] += e3 * pw[0][kw + 3];
            acc1[0] += e0 * pw[1][kw];     acc1[1] += e1 * pw[1][kw + 1];
            acc1[2] += e2 * pw[1][kw + 2]; acc1[3] += e3 * pw[1][kw + 3];
            acc2[0] += e0 * pw[2][kw];     acc2[1] += e1 * pw[2][kw + 1];
            acc2[2] += e2 * pw[2][kw + 2]; acc2[3] += e3 * pw[2][kw + 3];
        }

        fp += 7 * TAP;
    }

    // ---- epilogue: normalize + pixel shuffle ----
    // u -> (ur = u/4, uc = u%4); thread w's are wbase+4wg+i.
    const int ur = u >> 2, uc = u & 3;
    const int Ho = Hn * 4, Wo = Wn * 4;
    const size_t cstride = (size_t)Ho * Wo;
    size_t obase = ((size_t)(b * 3) * Ho + (4 * h + ur)) * Wo
                 + (size_t)4 * (wbase + 4 * wg) + uc;

    #pragma unroll
    for (int i = 0; i < 4; ++i) {
        float inv = 1.f / lsum[i];
        out[obase + 4 * i]                = acc0[i] * inv;
        out[obase + 4 * i + cstride]      = acc1[i] * inv;
        out[obase + 4 * i + 2 * cstride]  = acc2[i] * inv;
    }
}

extern "C" void kernel_launch(void* const* d_in, const int* in_sizes, int n_in,
                              void* d_out, int out_size)
{
    const float* x    = (const float*)d_in[0];   // [2,3,7,128,128]
    const float* filt = (const float*)d_in[1];   // [2,343,16,128,128]
    float* out        = (float*)d_out;           // [2,3,512,512]

    // NO carveout attribute: R12 proved maxing smem carveout guts L1 and
    // halves LDG MLP. 7 x 11.8KB = 82.6KB fits the default split fine.

    // grid = B * H * (W/WT) = 2*128*4 = 1024 blocks, 128 threads each.
    // 148 SMs x 7 resident = 1036 >= 1024 -> single wave, no tail.
    dynfilt_kernel<<<Bn * Hn * (Wn / WT), 128>>>(x, filt, out);
}

// round 14
// speedup vs baseline: 1.9315x; 1.0674x over previous
#include <cuda_runtime.h>

#define Bn   2
#define Tn   7
#define Hn   128
#define Wn   128
#define Pn   343            // 7*7*7 taps
#define Un   16
#define HW   (Hn*Wn)        // 16384
#define WT   16             // w-tile per block (per h row)
#define HT   2              // h rows per block
#define GH   8              // patch gh rows needed: 7 + HT - 1
#define RL   24             // padded patch row length (WT+6=22 -> 24, 16B-mult)
#define TSTR (GH*RL)        // per-t stride (floats)
#define CSTR (Tn*TSTR)      // per-channel stride (floats)

// R14: fp32 patches, 2 h-rows per block. The two rows' 7-row patch slabs
// overlap 6/7 -> union is 8 gh rows: smem 16.1KB (vs 24.1 fp32 / 12.0 fp16).
// 7 blocks x 16.1KB = 113KB fits the DEFAULT carveout (R12: never max it),
// so we get R13's single-wave residency AND drop R13's fp16 tax
// (18 LDS.32 + ~36 F2F per row -> 9 LDS.128, zero converts).
// Thread map: 128 thr = 16u x 2h x 4wg; each thread 1u, 1h, 4w (LDG.128).
// Inner loop = R3's proven phase-A/B front-batched structure.
// Fused softmax-without-max: filt (719MB) streamed exactly once via __ldcs.
__global__ __launch_bounds__(128, 7)
void dynfilt_kernel(const float* __restrict__ x,
                    const float* __restrict__ filt,
                    float* __restrict__ out)
{
    __shared__ float sm[3 * CSTR];   // 16.1 KB

    const int bx    = blockIdx.x;
    const int wq    = bx & 7;            // w eighth (8 tiles of 16)
    const int hp    = (bx >> 3) & 63;    // h pair index
    const int b     = bx >> 9;           // batch
    const int tid   = threadIdx.x;
    const int wg    = tid & 3;           // 0..3 -> w0 = 4*wg
    const int hh    = (tid >> 2) & 1;    // 0..1
    const int u     = tid >> 3;          // 0..15
    const int wbase = wq * WT;
    const int h0    = hp * HT;
    const int h     = h0 + hh;

    // ---- stage x patches (fp32): sm[((c*7+t)*8+g)*24 + j]
    //      g = gh-(h0-3) in [0,8), j = gw-(wbase-3) in [0,22), zero pad ----
    for (int idx = tid; idx < 3 * CSTR; idx += 128) {
        int j = idx % RL;
        int g = (idx / RL) % GH;
        int t = (idx / TSTR) % Tn;
        int c = idx / CSTR;
        int gh = h0 - 3 + g;
        int gw = wbase - 3 + j;
        float v = 0.f;
        if (j < WT + 6 && (unsigned)gh < (unsigned)Hn && (unsigned)gw < (unsigned)Wn)
            v = x[(((size_t)(b * 3 + c) * Tn + t) * Hn + gh) * Wn + gw];
        sm[idx] = v;
    }
    __syncthreads();

    float acc0[4] = {0.f, 0.f, 0.f, 0.f};   // channel 0, w0..w0+3
    float acc1[4] = {0.f, 0.f, 0.f, 0.f};
    float acc2[4] = {0.f, 0.f, 0.f, 0.f};
    float lsum[4] = {0.f, 0.f, 0.f, 0.f};

    // filt[b, p, u, h, w]; per-tap stride = Un*HW elems (1 MB).
    const size_t TAP = (size_t)Un * HW;
    const float* fp = filt + (((size_t)b * Pn) * Un + (size_t)u) * HW
                           + (size_t)h * Wn + wbase + 4 * wg;

    #pragma unroll 1
    for (int r = 0; r < 49; ++r) {
        const int t  = r / 7;
        const int kh = r % 7;
        // patch row for (t, kh) at this thread's h: g = hh + kh
        const float* srow = sm + t * TSTR + (hh + kh) * RL + 4 * wg;  // 16B aligned

        // ---- phase A: stage 4 taps (LDG.128) + patch window [0..7] ----
        float4 f0 = __ldcs((const float4*)(fp + 0 * TAP));
        float4 f1 = __ldcs((const float4*)(fp + 1 * TAP));
        float4 f2 = __ldcs((const float4*)(fp + 2 * TAP));
        float4 f3 = __ldcs((const float4*)(fp + 3 * TAP));

        float pw[3][12];
        #pragma unroll
        for (int c = 0; c < 3; ++c) {
            float4 q0 = *(const float4*)(srow + c * CSTR);
            float4 q1 = *(const float4*)(srow + c * CSTR + 4);
            pw[c][0] = q0.x; pw[c][1] = q0.y; pw[c][2] = q0.z; pw[c][3] = q0.w;
            pw[c][4] = q1.x; pw[c][5] = q1.y; pw[c][6] = q1.z; pw[c][7] = q1.w;
        }

        float4 fq[4] = {f0, f1, f2, f3};
        #pragma unroll
        for (int kw = 0; kw < 4; ++kw) {
            float e0 = __expf(fq[kw].x);
            float e1 = __expf(fq[kw].y);
            float e2 = __expf(fq[kw].z);
            float e3 = __expf(fq[kw].w);
            lsum[0] += e0; lsum[1] += e1; lsum[2] += e2; lsum[3] += e3;
            acc0[0] += e0 * pw[0][kw];     acc0[1] += e1 * pw[0][kw + 1];
            acc0[2] += e2 * pw[0][kw + 2]; acc0[3] += e3 * pw[0][kw + 3];
            acc1[0] += e0 * pw[1][kw];     acc1[1] += e1 * pw[1][kw + 1];
            acc1[2] += e2 * pw[1][kw + 2]; acc1[3] += e3 * pw[1][kw + 3];
            acc2[0] += e0 * pw[2][kw];     acc2[1] += e1 * pw[2][kw + 1];
            acc2[2] += e2 * pw[2][kw + 2]; acc2[3] += e3 * pw[2][kw + 3];
        }

        // ---- phase B: 3 taps + patch window [8..11] ----
        float4 g0 = __ldcs((const float4*)(fp + 4 * TAP));
        float4 g1 = __ldcs((const float4*)(fp + 5 * TAP));
        float4 g2 = __ldcs((const float4*)(fp + 6 * TAP));

        #pragma unroll
        for (int c = 0; c < 3; ++c) {
            float4 q2 = *(const float4*)(srow + c * CSTR + 8);
            pw[c][8] = q2.x; pw[c][9] = q2.y; pw[c][10] = q2.z; pw[c][11] = q2.w;
        }

        float4 gq[3] = {g0, g1, g2};
        #pragma unroll
        for (int k = 0; k < 3; ++k) {
            int kw = k + 4;
            float e0 = __expf(gq[k].x);
            float e1 = __expf(gq[k].y);
            float e2 = __expf(gq[k].z);
            float e3 = __expf(gq[k].w);
            lsum[0] += e0; lsum[1] += e1; lsum[2] += e2; lsum[3] += e3;
            acc0[0] += e0 * pw[0][kw];     acc0[1] += e1 * pw[0][kw + 1];
            acc0[2] += e2 * pw[0][kw + 2]; acc0[3] += e3 * pw[0][kw + 3];
            acc1[0] += e0 * pw[1][kw];     acc1[1] += e1 * pw[1][kw + 1];
            acc1[2] += e2 * pw[1][kw + 2]; acc1[3] += e3 * pw[1][kw + 3];
            acc2[0] += e0 * pw[2][kw];     acc2[1] += e1 * pw[2][kw + 1];
            acc2[2] += e2 * pw[2][kw + 2]; acc2[3] += e3 * pw[2][kw + 3];
        }

        fp += 7 * TAP;
    }

    // ---- epilogue: normalize + pixel shuffle ----
    // u -> (ur = u/4, uc = u%4); thread w's are wbase+4wg+i -> col 4w+uc.
    const int ur = u >> 2, uc = u & 3;
    const int Ho = Hn * 4, Wo = Wn * 4;
    const size_t cstride = (size_t)Ho * Wo;
    size_t obase = ((size_t)(b * 3) * Ho + (4 * h + ur)) * Wo
                 + (size_t)4 * (wbase + 4 * wg) + uc;

    #pragma unroll
    for (int i = 0; i < 4; ++i) {
        float inv = 1.f / lsum[i];
        out[obase + 4 * i]                = acc0[i] * inv;
        out[obase + 4 * i + cstride]      = acc1[i] * inv;
        out[obase + 4 * i + 2 * cstride]  = acc2[i] * inv;
    }
}

extern "C" void kernel_launch(void* const* d_in, const int* in_sizes, int n_in,
                              void* d_out, int out_size)
{
    const float* x    = (const float*)d_in[0];   // [2,3,7,128,128]
    const float* filt = (const float*)d_in[1];   // [2,343,16,128,128]
    float* out        = (float*)d_out;           // [2,3,512,512]

    // grid = B * (H/HT) * (W/WT) = 2*64*8 = 1024 blocks, 128 threads.
    // 148 SMs x 7 resident (16.1KB smem, <=72 regs) = 1036 >= 1024:
    // single wave, no tail. No carveout attribute (R12 lesson).
    dynfilt_kernel<<<Bn * (Hn / HT) * (Wn / WT), 128>>>(x, filt, out);
}